// round 14
// baseline (speedup 1.0000x reference)
#include <cuda_runtime.h>
#include <cuda_fp16.h>
#include <cstdint>
#include <cstddef>

// ---------------------------------------------------------------------------
// out = sigmoid(relu(x @ W1 + b1) @ W2 + b2)
// fp16 mma.sync (HMMA) GEMMs, fp32 accum.  Pre-tiled gmem scratch; stages
// loaded with 2 cp.async.bulk DMA ops; full/empty mbarrier pipeline.
// GEMM1 + GEMM2 FUSED into one grid: GEMM2 CTAs gate on per-m-row counters
// filled by GEMM1 CTAs -> GEMM2 fills GEMM1's tail waves and loses its own
// wave-quantization idle (512 CTAs / 296 slots was 13.5% idle).
// (tcgen05 unavailable: harness PTX targets base sm_103, not sm_103a)
// ---------------------------------------------------------------------------

#define DI __device__ __forceinline__

static constexpr int BATCH = 4096;
static constexpr int IN_F  = 2048;
static constexpr int HID_F = 8192;
static constexpr int OUT_F = 2048;

static constexpr int A_TILE   = 128 * 128;           // bytes (8192 halfs)
static constexpr int B_STRIDE = 272;                 // 256B data + 16B pad
static constexpr int B_TILE   = 64 * B_STRIDE;       // 17408 bytes
static constexpr int A_TILE_H = A_TILE / 2;
static constexpr int B_TILE_H = B_TILE / 2;

static constexpr int G1_CTAS = (HID_F / 128) * (BATCH / 128);   // 64*32 = 2048
static constexpr int G1_XDIM = HID_F / 128;                     // 64 tiles per m-row

// pre-tiled fp16 scratch
__device__ __align__(16) __half g_x [(size_t)(BATCH / 128) * (IN_F / 64) * A_TILE_H];
__device__ __align__(16) __half g_w1[(size_t)(HID_F / 128) * (IN_F / 64) * B_TILE_H];
__device__ __align__(16) __half g_w2[(size_t)(OUT_F / 128) * (HID_F / 64) * B_TILE_H];
__device__ __align__(16) __half g_h [(size_t)(BATCH / 128) * (HID_F / 64) * A_TILE_H];

__device__ int g_row_done[BATCH / 128];   // per-m-row GEMM1 completion counters

// ---------------------------------------------------------------------------
DI uint32_t smem_u32(const void* p) {
    uint32_t a;
    asm("{ .reg .u64 t; cvta.to.shared.u64 t, %1; cvt.u32.u64 %0, t; }"
        : "=r"(a) : "l"(p));
    return a;
}

DI void mbar_init(uint32_t a, uint32_t cnt) {
    asm volatile("mbarrier.init.shared.b64 [%0], %1;" :: "r"(a), "r"(cnt) : "memory");
}
DI void mbar_expect_tx(uint32_t a, uint32_t bytes) {
    asm volatile("mbarrier.arrive.expect_tx.shared.b64 _, [%0], %1;"
                 :: "r"(a), "r"(bytes) : "memory");
}
DI void mbar_arrive(uint32_t a) {
    asm volatile("mbarrier.arrive.shared.b64 _, [%0];" :: "r"(a) : "memory");
}
DI void mbar_wait(uint32_t a, uint32_t parity) {
    asm volatile(
        "{\n\t"
        ".reg .pred P;\n\t"
        "WAIT_%=:\n\t"
        "mbarrier.try_wait.parity.acquire.cta.shared::cta.b64 P, [%0], %1, 0x989680;\n\t"
        "@P bra.uni DONE_%=;\n\t"
        "bra.uni WAIT_%=;\n\t"
        "DONE_%=:\n\t"
        "}"
        :: "r"(a), "r"(parity) : "memory");
}

DI void bulk_g2s(uint32_t dst, const void* src, uint32_t bytes, uint32_t mbar) {
    asm volatile(
        "cp.async.bulk.shared::cluster.global.mbarrier::complete_tx::bytes "
        "[%0], [%1], %2, [%3];"
        :: "r"(dst), "l"(src), "r"(bytes), "r"(mbar) : "memory");
}

DI void ldm4(uint32_t* r, uint32_t addr) {
    asm volatile("ldmatrix.sync.aligned.m8n8.x4.shared.b16 {%0,%1,%2,%3}, [%4];"
                 : "=r"(r[0]), "=r"(r[1]), "=r"(r[2]), "=r"(r[3]) : "r"(addr));
}
DI void ldm4t(uint32_t* r, uint32_t addr) {
    asm volatile("ldmatrix.sync.aligned.m8n8.x4.trans.shared.b16 {%0,%1,%2,%3}, [%4];"
                 : "=r"(r[0]), "=r"(r[1]), "=r"(r[2]), "=r"(r[3]) : "r"(addr));
}

DI void mma16816(float* d, const uint32_t* a, uint32_t b0, uint32_t b1) {
    asm volatile(
        "mma.sync.aligned.m16n8k16.row.col.f32.f16.f16.f32 "
        "{%0,%1,%2,%3}, {%4,%5,%6,%7}, {%8,%9}, {%0,%1,%2,%3};"
        : "+f"(d[0]), "+f"(d[1]), "+f"(d[2]), "+f"(d[3])
        : "r"(a[0]), "r"(a[1]), "r"(a[2]), "r"(a[3]), "r"(b0), "r"(b1));
}

DI uint32_t sw128(uint32_t o) { return o ^ ((o >> 3) & 0x70); }

// ---------------------------------------------------------------------------
// Prep: f32 -> f16 converts writing the pre-tiled layouts
// ---------------------------------------------------------------------------
__global__ void convert_x_kernel(const float* __restrict__ x) {
    if (blockIdx.x == 0 && threadIdx.x < BATCH / 128)
        g_row_done[threadIdx.x] = 0;                       // reset per replay
    const int id = blockIdx.x * 256 + threadIdx.x;          // over M * K/8
    const int m  = id >> 8;                                 // K/8 = 256
    const int kc = id & 255;
    float4 v0 = *reinterpret_cast<const float4*>(x + (size_t)m * IN_F + kc * 8);
    float4 v1 = *reinterpret_cast<const float4*>(x + (size_t)m * IN_F + kc * 8 + 4);
    __half2 h[4];
    h[0] = __floats2half2_rn(v0.x, v0.y);
    h[1] = __floats2half2_rn(v0.z, v0.w);
    h[2] = __floats2half2_rn(v1.x, v1.y);
    h[3] = __floats2half2_rn(v1.z, v1.w);
    const int r = m & 127;
    const uint32_t inTile = (uint32_t)((r * 64 + (kc & 7) * 8) ^ ((r & 7) * 8)); // halfs
    const size_t tile = (size_t)(m >> 7) * (IN_F / 64) + (kc >> 3);
    *reinterpret_cast<uint4*>(&g_x[tile * A_TILE_H + inTile]) =
        *reinterpret_cast<const uint4*>(h);
}

template <int WHICH>   // 1: W1 (K=IN_F,N=HID_F), 2: W2 (K=HID_F,N=OUT_F)
__global__ void convert_w_kernel(const float* __restrict__ W) {
    constexpr int K = WHICH == 1 ? IN_F : HID_F;
    constexpr int N = WHICH == 1 ? HID_F : OUT_F;
    __half* dst = WHICH == 1 ? g_w1 : g_w2;
    const int id = blockIdx.x * 256 + threadIdx.x;          // over K * N/8
    const int k  = id / (N / 8);
    const int nc = id % (N / 8);
    float4 v0 = *reinterpret_cast<const float4*>(W + (size_t)k * N + nc * 8);
    float4 v1 = *reinterpret_cast<const float4*>(W + (size_t)k * N + nc * 8 + 4);
    __half2 h[4];
    h[0] = __floats2half2_rn(v0.x, v0.y);
    h[1] = __floats2half2_rn(v0.z, v0.w);
    h[2] = __floats2half2_rn(v1.x, v1.y);
    h[3] = __floats2half2_rn(v1.z, v1.w);
    const size_t tile = (size_t)(nc >> 4) * (K / 64) + (k >> 6);
    const uint32_t inTile = (uint32_t)((k & 63) * 136 + (nc & 15) * 8);  // halfs
    *reinterpret_cast<uint4*>(&dst[tile * B_TILE_H + inTile]) =
        *reinterpret_cast<const uint4*>(h);
}

// ---------------------------------------------------------------------------
// Fused GEMM: bids [0, G1_CTAS) = GEMM1 tiles; rest = GEMM2 tiles.
// per-CTA 128x128, K-chunk 64, 3-stage bulk-DMA pipeline, full/empty mbars.
// 256 threads = 8 warps as 4(M) x 2(N); warp tile 32x64.
// ---------------------------------------------------------------------------
static constexpr int NSTAGE = 3;
static constexpr int STAGE_BYTES = A_TILE + B_TILE;   // 33792
static constexpr uint32_t STAGE_TX = (uint32_t)STAGE_BYTES;
static constexpr int SMEM_DYN = 1024 + NSTAGE * STAGE_BYTES;   // 102400

__global__ __launch_bounds__(256, 2)
void gemm_fused_kernel(const float* __restrict__ b1, const float* __restrict__ b2,
                       float* __restrict__ out_f32) {
    const int bid = blockIdx.x;
    const bool g2 = bid >= G1_CTAS;

    int bx, by, nIter;
    const __half *Ab, *Bb;
    const float* bias;
    if (!g2) {
        bx = bid & (G1_XDIM - 1); by = bid >> 6;          // 64 tiles per m-row
        nIter = IN_F / 64;
        Ab = g_x + (size_t)by * (IN_F / 64) * A_TILE_H;
        Bb = g_w1 + (size_t)bx * (IN_F / 64) * B_TILE_H;
        bias = b1;
    } else {
        const int b2i = bid - G1_CTAS;
        bx = b2i & 15; by = b2i >> 4;                      // 16 tiles per m-row
        nIter = HID_F / 64;
        Ab = g_h + (size_t)by * (HID_F / 64) * A_TILE_H;
        Bb = g_w2 + (size_t)bx * (HID_F / 64) * B_TILE_H;
        bias = b2;
    }
    const char* gA = (const char*)Ab;
    const char* gB = (const char*)Bb;

    extern __shared__ char smem_raw[];
    const uint32_t ctrl  = (smem_u32(smem_raw) + 15) & ~15u;
    const uint32_t sbase = (ctrl + 1023) & ~1023u;
    // full[s] = ctrl + 8*s ; empty[s] = ctrl + 24 + 8*s

    const int tid  = threadIdx.x;
    const int lane = tid & 31;
    const int warp = tid >> 5;
    const int wm   = warp & 3;
    const int wn   = warp >> 2;
    const int mBase = by * 128;
    const int nBase = bx * 128;

    if (tid == 0) {
#pragma unroll
        for (int s = 0; s < NSTAGE; ++s) {
            mbar_init(ctrl + 8 * s, 1);
            mbar_init(ctrl + 24 + 8 * s, 256);
        }
        if (g2) {
            // wait for all 64 GEMM1 tiles of this m-row
            volatile int* flag = &g_row_done[by];
            while (*flag < G1_XDIM) {}
            __threadfence();
        }
    }
    __syncthreads();

    float acc[2][8][4];
#pragma unroll
    for (int i = 0; i < 2; ++i)
#pragma unroll
        for (int j = 0; j < 8; ++j)
#pragma unroll
            for (int k = 0; k < 4; ++k) acc[i][j][k] = 0.0f;

    // prologue: all three stages in flight
    if (tid == 0) {
#pragma unroll
        for (int s = 0; s < NSTAGE; ++s) {
            const uint32_t mb = ctrl + 8 * s;
            const uint32_t As = sbase + s * STAGE_BYTES;
            mbar_expect_tx(mb, STAGE_TX);
            bulk_g2s(As,          gA + (size_t)s * A_TILE, A_TILE, mb);
            bulk_g2s(As + A_TILE, gB + (size_t)s * B_TILE, B_TILE, mb);
        }
    }

    const uint32_t aRowOff = (uint32_t)((wm * 32 + (lane & 15)) * 128 + ((lane >> 4) << 4));
    const int q = lane >> 3, r = lane & 7;
    const uint32_t bAddrBase = (uint32_t)(((q & 1) * 8 + r) * B_STRIDE
                                          + (wn * 64 + (q >> 1) * 8) * 2);

    int fph0 = 0, fph1 = 0, fph2 = 0;
    int eph0 = 0, eph1 = 0, eph2 = 0;
    int s = 0;
#pragma unroll 1
    for (int it = 0; it < nIter; ++it) {
        const uint32_t fullB  = ctrl + 8 * s;
        const uint32_t emptyB = ctrl + 24 + 8 * s;
        if (s == 0)      { mbar_wait(fullB, fph0); fph0 ^= 1; }
        else if (s == 1) { mbar_wait(fullB, fph1); fph1 ^= 1; }
        else             { mbar_wait(fullB, fph2); fph2 ^= 1; }

        const uint32_t As = sbase + s * STAGE_BYTES;
        const uint32_t Bs = As + A_TILE;

#pragma unroll
        for (int ks = 0; ks < 4; ++ks) {
            uint32_t a[2][4], b[4][4];
#pragma unroll
            for (int mt = 0; mt < 2; ++mt)
                ldm4(a[mt], As + sw128(aRowOff + mt * 16 * 128 + ks * 32));
            const uint32_t bs = Bs + bAddrBase + (uint32_t)(ks * 16 * B_STRIDE);
#pragma unroll
            for (int nb = 0; nb < 4; ++nb)
                ldm4t(b[nb], bs + nb * 32);
#pragma unroll
            for (int mt = 0; mt < 2; ++mt)
#pragma unroll
                for (int nt = 0; nt < 8; ++nt) {
                    const uint32_t* bb = b[nt >> 1];
                    if (nt & 1) mma16816(acc[mt][nt], a[mt], bb[2], bb[3]);
                    else        mma16816(acc[mt][nt], a[mt], bb[0], bb[1]);
                }
        }

        mbar_arrive(emptyB);

        if (it + NSTAGE < nIter && tid == 0) {
            if (s == 0)      { mbar_wait(emptyB, eph0); eph0 ^= 1; }
            else if (s == 1) { mbar_wait(emptyB, eph1); eph1 ^= 1; }
            else             { mbar_wait(emptyB, eph2); eph2 ^= 1; }
            mbar_expect_tx(fullB, STAGE_TX);
            bulk_g2s(As,          gA + (size_t)(it + NSTAGE) * A_TILE, A_TILE, fullB);
            bulk_g2s(As + A_TILE, gB + (size_t)(it + NSTAGE) * B_TILE, B_TILE, fullB);
        }
        if (++s == NSTAGE) s = 0;
    }

    // epilogue
#pragma unroll
    for (int mt = 0; mt < 2; ++mt) {
#pragma unroll
        for (int nt = 0; nt < 8; ++nt) {
            const int col = nBase + wn * 64 + nt * 8 + (lane & 3) * 2;
            const float bv0 = __ldg(&bias[col]);
            const float bv1 = __ldg(&bias[col + 1]);
#pragma unroll
            for (int rr = 0; rr < 2; ++rr) {
                const int row = mBase + wm * 32 + mt * 16 + (lane >> 2) + rr * 8;
                float v0 = acc[mt][nt][rr * 2 + 0] + bv0;
                float v1 = acc[mt][nt][rr * 2 + 1] + bv1;
                if (!g2) {
                    // write g_h in tiled+swizzled A-tile layout for GEMM2
                    __half2 h = __floats2half2_rn(fmaxf(v0, 0.0f), fmaxf(v1, 0.0f));
                    const int rr_ = row & 127;
                    const size_t tile = (size_t)(row >> 7) * (HID_F / 64) + (col >> 6);
                    const uint32_t inTile =
                        (uint32_t)(rr_ * 128 + (col & 63) * 2) ^ (uint32_t)((rr_ & 7) << 4);
                    *reinterpret_cast<__half2*>(
                        (char*)g_h + tile * A_TILE + inTile) = h;
                } else {
                    float2 o;
                    o.x = 1.0f / (1.0f + __expf(-v0));
                    o.y = 1.0f / (1.0f + __expf(-v1));
                    *reinterpret_cast<float2*>(&out_f32[(size_t)row * OUT_F + col]) = o;
                }
            }
        }
    }

    if (!g2) {
        // publish this GEMM1 tile's completion for its m-row
        __threadfence();
        __syncthreads();
        if (tid == 0) atomicAdd(&g_row_done[by], 1);
    }
}

// ---------------------------------------------------------------------------
extern "C" void kernel_launch(void* const* d_in, const int* in_sizes, int n_in,
                              void* d_out, int out_size) {
    (void)in_sizes; (void)n_in; (void)out_size;
    const float* x  = (const float*)d_in[0];
    const float* W1 = (const float*)d_in[1];
    const float* b1 = (const float*)d_in[2];
    const float* W2 = (const float*)d_in[3];
    const float* b2 = (const float*)d_in[4];
    float* out = (float*)d_out;

    cudaFuncSetAttribute(gemm_fused_kernel,
                         cudaFuncAttributeMaxDynamicSharedMemorySize, SMEM_DYN);

    convert_x_kernel<<<(BATCH * (IN_F / 8)) / 256, 256>>>(x);
    convert_w_kernel<1><<<(IN_F * (HID_F / 8)) / 256, 256>>>(W1);
    convert_w_kernel<2><<<(HID_F * (OUT_F / 8)) / 256, 256>>>(W2);

    const int totalCtas = G1_CTAS + (OUT_F / 128) * (BATCH / 128);  // 2048 + 512
    gemm_fused_kernel<<<totalCtas, 256, SMEM_DYN>>>(b1, b2, out);
}

// round 15
// speedup vs baseline: 1.0066x; 1.0066x over previous
#include <cuda_runtime.h>
#include <cuda_fp16.h>
#include <cstdint>
#include <cstddef>

// ---------------------------------------------------------------------------
// out = sigmoid(relu(x @ W1 + b1) @ W2 + b2)
// fp16 mma.sync (HMMA) GEMMs, fp32 accum.
// Pre-tiled gmem scratch; stages loaded with 2 cp.async.bulk DMA ops;
// full/empty mbarrier pipeline (no mainloop __syncthreads).
// 4 warps/CTA (2x2), warp tile 64x64 -> 32 dependency-free HMMAs per ldsm
// batch (double the latency-hiding chain of 32x64), half the ldsm issue.
// (tcgen05 unavailable: harness PTX targets base sm_103, not sm_103a)
// ---------------------------------------------------------------------------

#define DI __device__ __forceinline__

static constexpr int BATCH = 4096;
static constexpr int IN_F  = 2048;
static constexpr int HID_F = 8192;
static constexpr int OUT_F = 2048;

static constexpr int A_TILE   = 128 * 128;           // bytes (8192 halfs)
static constexpr int B_STRIDE = 272;                 // 256B data + 16B pad
static constexpr int B_TILE   = 64 * B_STRIDE;       // 17408 bytes
static constexpr int A_TILE_H = A_TILE / 2;
static constexpr int B_TILE_H = B_TILE / 2;

// pre-tiled fp16 scratch
__device__ __align__(16) __half g_x [(size_t)(BATCH / 128) * (IN_F / 64) * A_TILE_H];
__device__ __align__(16) __half g_w1[(size_t)(HID_F / 128) * (IN_F / 64) * B_TILE_H];
__device__ __align__(16) __half g_w2[(size_t)(OUT_F / 128) * (HID_F / 64) * B_TILE_H];
__device__ __align__(16) __half g_h [(size_t)(BATCH / 128) * (HID_F / 64) * A_TILE_H];

// ---------------------------------------------------------------------------
DI uint32_t smem_u32(const void* p) {
    uint32_t a;
    asm("{ .reg .u64 t; cvta.to.shared.u64 t, %1; cvt.u32.u64 %0, t; }"
        : "=r"(a) : "l"(p));
    return a;
}

DI void mbar_init(uint32_t a, uint32_t cnt) {
    asm volatile("mbarrier.init.shared.b64 [%0], %1;" :: "r"(a), "r"(cnt) : "memory");
}
DI void mbar_expect_tx(uint32_t a, uint32_t bytes) {
    asm volatile("mbarrier.arrive.expect_tx.shared.b64 _, [%0], %1;"
                 :: "r"(a), "r"(bytes) : "memory");
}
DI void mbar_arrive(uint32_t a) {
    asm volatile("mbarrier.arrive.shared.b64 _, [%0];" :: "r"(a) : "memory");
}
DI void mbar_wait(uint32_t a, uint32_t parity) {
    asm volatile(
        "{\n\t"
        ".reg .pred P;\n\t"
        "WAIT_%=:\n\t"
        "mbarrier.try_wait.parity.acquire.cta.shared::cta.b64 P, [%0], %1, 0x989680;\n\t"
        "@P bra.uni DONE_%=;\n\t"
        "bra.uni WAIT_%=;\n\t"
        "DONE_%=:\n\t"
        "}"
        :: "r"(a), "r"(parity) : "memory");
}

DI void bulk_g2s(uint32_t dst, const void* src, uint32_t bytes, uint32_t mbar) {
    asm volatile(
        "cp.async.bulk.shared::cluster.global.mbarrier::complete_tx::bytes "
        "[%0], [%1], %2, [%3];"
        :: "r"(dst), "l"(src), "r"(bytes), "r"(mbar) : "memory");
}

DI void ldm4(uint32_t* r, uint32_t addr) {
    asm volatile("ldmatrix.sync.aligned.m8n8.x4.shared.b16 {%0,%1,%2,%3}, [%4];"
                 : "=r"(r[0]), "=r"(r[1]), "=r"(r[2]), "=r"(r[3]) : "r"(addr));
}
DI void ldm4t(uint32_t* r, uint32_t addr) {
    asm volatile("ldmatrix.sync.aligned.m8n8.x4.trans.shared.b16 {%0,%1,%2,%3}, [%4];"
                 : "=r"(r[0]), "=r"(r[1]), "=r"(r[2]), "=r"(r[3]) : "r"(addr));
}

DI void mma16816(float* d, const uint32_t* a, uint32_t b0, uint32_t b1) {
    asm volatile(
        "mma.sync.aligned.m16n8k16.row.col.f32.f16.f16.f32 "
        "{%0,%1,%2,%3}, {%4,%5,%6,%7}, {%8,%9}, {%0,%1,%2,%3};"
        : "+f"(d[0]), "+f"(d[1]), "+f"(d[2]), "+f"(d[3])
        : "r"(a[0]), "r"(a[1]), "r"(a[2]), "r"(a[3]), "r"(b0), "r"(b1));
}

DI uint32_t sw128(uint32_t o) { return o ^ ((o >> 3) & 0x70); }

// ---------------------------------------------------------------------------
// Prep: f32 -> f16 converts writing the pre-tiled layouts
// ---------------------------------------------------------------------------
__global__ void convert_x_kernel(const float* __restrict__ x) {
    const int id = blockIdx.x * 256 + threadIdx.x;          // over M * K/8
    const int m  = id >> 8;                                 // K/8 = 256
    const int kc = id & 255;
    float4 v0 = *reinterpret_cast<const float4*>(x + (size_t)m * IN_F + kc * 8);
    float4 v1 = *reinterpret_cast<const float4*>(x + (size_t)m * IN_F + kc * 8 + 4);
    __half2 h[4];
    h[0] = __floats2half2_rn(v0.x, v0.y);
    h[1] = __floats2half2_rn(v0.z, v0.w);
    h[2] = __floats2half2_rn(v1.x, v1.y);
    h[3] = __floats2half2_rn(v1.z, v1.w);
    const int r = m & 127;
    const uint32_t inTile = (uint32_t)((r * 64 + (kc & 7) * 8) ^ ((r & 7) * 8)); // halfs
    const size_t tile = (size_t)(m >> 7) * (IN_F / 64) + (kc >> 3);
    *reinterpret_cast<uint4*>(&g_x[tile * A_TILE_H + inTile]) =
        *reinterpret_cast<const uint4*>(h);
}

template <int WHICH>   // 1: W1 (K=IN_F,N=HID_F), 2: W2 (K=HID_F,N=OUT_F)
__global__ void convert_w_kernel(const float* __restrict__ W) {
    constexpr int K = WHICH == 1 ? IN_F : HID_F;
    constexpr int N = WHICH == 1 ? HID_F : OUT_F;
    __half* dst = WHICH == 1 ? g_w1 : g_w2;
    const int id = blockIdx.x * 256 + threadIdx.x;          // over K * N/8
    const int k  = id / (N / 8);
    const int nc = id % (N / 8);
    float4 v0 = *reinterpret_cast<const float4*>(W + (size_t)k * N + nc * 8);
    float4 v1 = *reinterpret_cast<const float4*>(W + (size_t)k * N + nc * 8 + 4);
    __half2 h[4];
    h[0] = __floats2half2_rn(v0.x, v0.y);
    h[1] = __floats2half2_rn(v0.z, v0.w);
    h[2] = __floats2half2_rn(v1.x, v1.y);
    h[3] = __floats2half2_rn(v1.z, v1.w);
    const size_t tile = (size_t)(nc >> 4) * (K / 64) + (k >> 6);
    const uint32_t inTile = (uint32_t)((k & 63) * 136 + (nc & 15) * 8);  // halfs
    *reinterpret_cast<uint4*>(&dst[tile * B_TILE_H + inTile]) =
        *reinterpret_cast<const uint4*>(h);
}

// ---------------------------------------------------------------------------
// GEMM: per-CTA 128x128, K-chunk 64, 3-stage bulk-DMA pipeline with
// full/empty mbarrier pairs.  128 threads = 4 warps as 2(M) x 2(N);
// warp tile 64x64.
// ---------------------------------------------------------------------------
static constexpr int NSTAGE = 3;
static constexpr int STAGE_BYTES = A_TILE + B_TILE;   // 33792
static constexpr uint32_t STAGE_TX = (uint32_t)STAGE_BYTES;
static constexpr int SMEM_DYN = 1024 + NSTAGE * STAGE_BYTES;   // 102400

template <int EPI>
__global__ __launch_bounds__(128, 2)
void gemm_kernel(const float* __restrict__ bias, float* __restrict__ out_f32) {
    constexpr int KDIM  = EPI ? HID_F : IN_F;
    constexpr int NITER = KDIM / 64;
    const __half* A = EPI ? g_h  : g_x;
    const __half* B = EPI ? g_w2 : g_w1;

    extern __shared__ char smem_raw[];
    const uint32_t ctrl  = (smem_u32(smem_raw) + 15) & ~15u;
    const uint32_t sbase = (ctrl + 1023) & ~1023u;
    // full[s] = ctrl + 8*s ; empty[s] = ctrl + 24 + 8*s

    const int tid  = threadIdx.x;
    const int lane = tid & 31;
    const int warp = tid >> 5;
    const int wm   = warp & 1;    // 2 warps along M (64 rows each)
    const int wn   = warp >> 1;   // 2 warps along N (64 cols each)
    const int mBase = blockIdx.y * 128;
    const int nBase = blockIdx.x * 128;

    const char* gA = (const char*)(A + (size_t)blockIdx.y * (KDIM / 64) * A_TILE_H);
    const char* gB = (const char*)(B + (size_t)blockIdx.x * (KDIM / 64) * B_TILE_H);

    if (tid == 0) {
#pragma unroll
        for (int s = 0; s < NSTAGE; ++s) {
            mbar_init(ctrl + 8 * s, 1);        // full: completed by DMA tx
            mbar_init(ctrl + 24 + 8 * s, 128); // empty: all consumers arrive
        }
    }
    __syncthreads();

    float acc[4][8][4];   // [mt 16-rows][nt 8-cols][frag] = 128 regs
#pragma unroll
    for (int i = 0; i < 4; ++i)
#pragma unroll
        for (int j = 0; j < 8; ++j)
#pragma unroll
            for (int k = 0; k < 4; ++k) acc[i][j][k] = 0.0f;

    // prologue: all three stages in flight
    if (tid == 0) {
#pragma unroll
        for (int s = 0; s < NSTAGE; ++s) {
            const uint32_t mb = ctrl + 8 * s;
            const uint32_t As = sbase + s * STAGE_BYTES;
            mbar_expect_tx(mb, STAGE_TX);
            bulk_g2s(As,          gA + (size_t)s * A_TILE, A_TILE, mb);
            bulk_g2s(As + A_TILE, gB + (size_t)s * B_TILE, B_TILE, mb);
        }
    }

    const uint32_t aRowOff = (uint32_t)((wm * 64 + (lane & 15)) * 128 + ((lane >> 4) << 4));
    const int q = lane >> 3, r = lane & 7;
    const uint32_t bAddrBase = (uint32_t)(((q & 1) * 8 + r) * B_STRIDE
                                          + (wn * 64 + (q >> 1) * 8) * 2);

    int fph0 = 0, fph1 = 0, fph2 = 0;     // consumer full phases
    int eph0 = 0, eph1 = 0, eph2 = 0;     // producer empty phases (tid0)
    int s = 0;
#pragma unroll 1
    for (int it = 0; it < NITER; ++it) {
        const uint32_t fullB  = ctrl + 8 * s;
        const uint32_t emptyB = ctrl + 24 + 8 * s;
        if (s == 0)      { mbar_wait(fullB, fph0); fph0 ^= 1; }
        else if (s == 1) { mbar_wait(fullB, fph1); fph1 ^= 1; }
        else             { mbar_wait(fullB, fph2); fph2 ^= 1; }

        const uint32_t As = sbase + s * STAGE_BYTES;
        const uint32_t Bs = As + A_TILE;

#pragma unroll
        for (int ks = 0; ks < 4; ++ks) {
            uint32_t a[4][4], b[4][4];
#pragma unroll
            for (int mt = 0; mt < 4; ++mt)
                ldm4(a[mt], As + sw128(aRowOff + mt * 16 * 128 + ks * 32));
            const uint32_t bs = Bs + bAddrBase + (uint32_t)(ks * 16 * B_STRIDE);
#pragma unroll
            for (int nb = 0; nb < 4; ++nb)
                ldm4t(b[nb], bs + nb * 32);
#pragma unroll
            for (int mt = 0; mt < 4; ++mt)
#pragma unroll
                for (int nt = 0; nt < 8; ++nt) {
                    const uint32_t* bb = b[nt >> 1];
                    if (nt & 1) mma16816(acc[mt][nt], a[mt], bb[2], bb[3]);
                    else        mma16816(acc[mt][nt], a[mt], bb[0], bb[1]);
                }
        }

        // done reading stage s: non-blocking arrive, then free-run ahead
        mbar_arrive(emptyB);

        if (it + NSTAGE < NITER && tid == 0) {
            if (s == 0)      { mbar_wait(emptyB, eph0); eph0 ^= 1; }
            else if (s == 1) { mbar_wait(emptyB, eph1); eph1 ^= 1; }
            else             { mbar_wait(emptyB, eph2); eph2 ^= 1; }
            mbar_expect_tx(fullB, STAGE_TX);
            bulk_g2s(As,          gA + (size_t)(it + NSTAGE) * A_TILE, A_TILE, fullB);
            bulk_g2s(As + A_TILE, gB + (size_t)(it + NSTAGE) * B_TILE, B_TILE, fullB);
        }
        if (++s == NSTAGE) s = 0;
    }

    // epilogue
#pragma unroll
    for (int mt = 0; mt < 4; ++mt) {
#pragma unroll
        for (int nt = 0; nt < 8; ++nt) {
            const int col = nBase + wn * 64 + nt * 8 + (lane & 3) * 2;
            const float bv0 = __ldg(&bias[col]);
            const float bv1 = __ldg(&bias[col + 1]);
#pragma unroll
            for (int rr = 0; rr < 2; ++rr) {
                const int row = mBase + wm * 64 + mt * 16 + (lane >> 2) + rr * 8;
                float v0 = acc[mt][nt][rr * 2 + 0] + bv0;
                float v1 = acc[mt][nt][rr * 2 + 1] + bv1;
                if (EPI == 0) {
                    // write g_h in tiled+swizzled A-tile layout for GEMM2
                    __half2 h = __floats2half2_rn(fmaxf(v0, 0.0f), fmaxf(v1, 0.0f));
                    const int rr_ = row & 127;
                    const size_t tile = (size_t)(row >> 7) * (HID_F / 64) + (col >> 6);
                    const uint32_t inTile =
                        (uint32_t)(rr_ * 128 + (col & 63) * 2) ^ (uint32_t)((rr_ & 7) << 4);
                    *reinterpret_cast<__half2*>(
                        (char*)g_h + tile * A_TILE + inTile) = h;
                } else {
                    float2 o;
                    o.x = 1.0f / (1.0f + __expf(-v0));
                    o.y = 1.0f / (1.0f + __expf(-v1));
                    *reinterpret_cast<float2*>(&out_f32[(size_t)row * OUT_F + col]) = o;
                }
            }
        }
    }
}

// ---------------------------------------------------------------------------
extern "C" void kernel_launch(void* const* d_in, const int* in_sizes, int n_in,
                              void* d_out, int out_size) {
    (void)in_sizes; (void)n_in; (void)out_size;
    const float* x  = (const float*)d_in[0];
    const float* W1 = (const float*)d_in[1];
    const float* b1 = (const float*)d_in[2];
    const float* W2 = (const float*)d_in[3];
    const float* b2 = (const float*)d_in[4];
    float* out = (float*)d_out;

    cudaFuncSetAttribute(gemm_kernel<0>, cudaFuncAttributeMaxDynamicSharedMemorySize, SMEM_DYN);
    cudaFuncSetAttribute(gemm_kernel<1>, cudaFuncAttributeMaxDynamicSharedMemorySize, SMEM_DYN);

    convert_x_kernel<<<(BATCH * (IN_F / 8)) / 256, 256>>>(x);
    convert_w_kernel<1><<<(IN_F * (HID_F / 8)) / 256, 256>>>(W1);
    convert_w_kernel<2><<<(HID_F * (OUT_F / 8)) / 256, 256>>>(W2);

    // GEMM1: H = relu(x @ W1 + b1) -> fp16 g_h (tiled)
    gemm_kernel<0><<<dim3(HID_F / 128, BATCH / 128), 128, SMEM_DYN>>>(b1, nullptr);
    // GEMM2: out = sigmoid(H @ W2 + b2) -> f32 d_out
    gemm_kernel<1><<<dim3(OUT_F / 128, BATCH / 128), 128, SMEM_DYN>>>(b2, out);
}

// round 16
// speedup vs baseline: 1.0078x; 1.0012x over previous
#include <cuda_runtime.h>
#include <cuda_fp16.h>
#include <cstdint>
#include <cstddef>

// ---------------------------------------------------------------------------
// out = sigmoid(relu(x @ W1 + b1) @ W2 + b2)
// fp16 mma.sync (HMMA) GEMMs, fp32 accum.
// Pre-tiled gmem scratch; stages loaded with 2 cp.async.bulk DMA ops;
// full/empty mbarrier pipeline; 4 warps/CTA (2x2), warp tile 64x64.
// convert_w2 runs on a second stream concurrently with GEMM1 (fork/join
// events inside the captured graph) -> its ~22us leaves the critical path.
// (tcgen05 unavailable: harness PTX targets base sm_103, not sm_103a)
// ---------------------------------------------------------------------------

#define DI __device__ __forceinline__

static constexpr int BATCH = 4096;
static constexpr int IN_F  = 2048;
static constexpr int HID_F = 8192;
static constexpr int OUT_F = 2048;

static constexpr int A_TILE   = 128 * 128;           // bytes (8192 halfs)
static constexpr int B_STRIDE = 272;                 // 256B data + 16B pad
static constexpr int B_TILE   = 64 * B_STRIDE;       // 17408 bytes
static constexpr int A_TILE_H = A_TILE / 2;
static constexpr int B_TILE_H = B_TILE / 2;

// pre-tiled fp16 scratch
__device__ __align__(16) __half g_x [(size_t)(BATCH / 128) * (IN_F / 64) * A_TILE_H];
__device__ __align__(16) __half g_w1[(size_t)(HID_F / 128) * (IN_F / 64) * B_TILE_H];
__device__ __align__(16) __half g_w2[(size_t)(OUT_F / 128) * (HID_F / 64) * B_TILE_H];
__device__ __align__(16) __half g_h [(size_t)(BATCH / 128) * (HID_F / 64) * A_TILE_H];

// ---------------------------------------------------------------------------
DI uint32_t smem_u32(const void* p) {
    uint32_t a;
    asm("{ .reg .u64 t; cvta.to.shared.u64 t, %1; cvt.u32.u64 %0, t; }"
        : "=r"(a) : "l"(p));
    return a;
}

DI void mbar_init(uint32_t a, uint32_t cnt) {
    asm volatile("mbarrier.init.shared.b64 [%0], %1;" :: "r"(a), "r"(cnt) : "memory");
}
DI void mbar_expect_tx(uint32_t a, uint32_t bytes) {
    asm volatile("mbarrier.arrive.expect_tx.shared.b64 _, [%0], %1;"
                 :: "r"(a), "r"(bytes) : "memory");
}
DI void mbar_arrive(uint32_t a) {
    asm volatile("mbarrier.arrive.shared.b64 _, [%0];" :: "r"(a) : "memory");
}
DI void mbar_wait(uint32_t a, uint32_t parity) {
    asm volatile(
        "{\n\t"
        ".reg .pred P;\n\t"
        "WAIT_%=:\n\t"
        "mbarrier.try_wait.parity.acquire.cta.shared::cta.b64 P, [%0], %1, 0x989680;\n\t"
        "@P bra.uni DONE_%=;\n\t"
        "bra.uni WAIT_%=;\n\t"
        "DONE_%=:\n\t"
        "}"
        :: "r"(a), "r"(parity) : "memory");
}

DI void bulk_g2s(uint32_t dst, const void* src, uint32_t bytes, uint32_t mbar) {
    asm volatile(
        "cp.async.bulk.shared::cluster.global.mbarrier::complete_tx::bytes "
        "[%0], [%1], %2, [%3];"
        :: "r"(dst), "l"(src), "r"(bytes), "r"(mbar) : "memory");
}

DI void ldm4(uint32_t* r, uint32_t addr) {
    asm volatile("ldmatrix.sync.aligned.m8n8.x4.shared.b16 {%0,%1,%2,%3}, [%4];"
                 : "=r"(r[0]), "=r"(r[1]), "=r"(r[2]), "=r"(r[3]) : "r"(addr));
}
DI void ldm4t(uint32_t* r, uint32_t addr) {
    asm volatile("ldmatrix.sync.aligned.m8n8.x4.trans.shared.b16 {%0,%1,%2,%3}, [%4];"
                 : "=r"(r[0]), "=r"(r[1]), "=r"(r[2]), "=r"(r[3]) : "r"(addr));
}

DI void mma16816(float* d, const uint32_t* a, uint32_t b0, uint32_t b1) {
    asm volatile(
        "mma.sync.aligned.m16n8k16.row.col.f32.f16.f16.f32 "
        "{%0,%1,%2,%3}, {%4,%5,%6,%7}, {%8,%9}, {%0,%1,%2,%3};"
        : "+f"(d[0]), "+f"(d[1]), "+f"(d[2]), "+f"(d[3])
        : "r"(a[0]), "r"(a[1]), "r"(a[2]), "r"(a[3]), "r"(b0), "r"(b1));
}

DI uint32_t sw128(uint32_t o) { return o ^ ((o >> 3) & 0x70); }

// ---------------------------------------------------------------------------
// Prep: f32 -> f16 converts writing the pre-tiled layouts
// ---------------------------------------------------------------------------
__global__ void convert_x_kernel(const float* __restrict__ x) {
    const int id = blockIdx.x * 256 + threadIdx.x;          // over M * K/8
    const int m  = id >> 8;                                 // K/8 = 256
    const int kc = id & 255;
    float4 v0 = *reinterpret_cast<const float4*>(x + (size_t)m * IN_F + kc * 8);
    float4 v1 = *reinterpret_cast<const float4*>(x + (size_t)m * IN_F + kc * 8 + 4);
    __half2 h[4];
    h[0] = __floats2half2_rn(v0.x, v0.y);
    h[1] = __floats2half2_rn(v0.z, v0.w);
    h[2] = __floats2half2_rn(v1.x, v1.y);
    h[3] = __floats2half2_rn(v1.z, v1.w);
    const int r = m & 127;
    const uint32_t inTile = (uint32_t)((r * 64 + (kc & 7) * 8) ^ ((r & 7) * 8)); // halfs
    const size_t tile = (size_t)(m >> 7) * (IN_F / 64) + (kc >> 3);
    *reinterpret_cast<uint4*>(&g_x[tile * A_TILE_H + inTile]) =
        *reinterpret_cast<const uint4*>(h);
}

template <int WHICH>   // 1: W1 (K=IN_F,N=HID_F), 2: W2 (K=HID_F,N=OUT_F)
__global__ void convert_w_kernel(const float* __restrict__ W) {
    constexpr int K = WHICH == 1 ? IN_F : HID_F;
    constexpr int N = WHICH == 1 ? HID_F : OUT_F;
    __half* dst = WHICH == 1 ? g_w1 : g_w2;
    const int id = blockIdx.x * 256 + threadIdx.x;          // over K * N/8
    const int k  = id / (N / 8);
    const int nc = id % (N / 8);
    float4 v0 = *reinterpret_cast<const float4*>(W + (size_t)k * N + nc * 8);
    float4 v1 = *reinterpret_cast<const float4*>(W + (size_t)k * N + nc * 8 + 4);
    __half2 h[4];
    h[0] = __floats2half2_rn(v0.x, v0.y);
    h[1] = __floats2half2_rn(v0.z, v0.w);
    h[2] = __floats2half2_rn(v1.x, v1.y);
    h[3] = __floats2half2_rn(v1.z, v1.w);
    const size_t tile = (size_t)(nc >> 4) * (K / 64) + (k >> 6);
    const uint32_t inTile = (uint32_t)((k & 63) * 136 + (nc & 15) * 8);  // halfs
    *reinterpret_cast<uint4*>(&dst[tile * B_TILE_H + inTile]) =
        *reinterpret_cast<const uint4*>(h);
}

// ---------------------------------------------------------------------------
// GEMM: per-CTA 128x128, K-chunk 64, 3-stage bulk-DMA pipeline with
// full/empty mbarrier pairs.  128 threads = 4 warps as 2(M) x 2(N);
// warp tile 64x64.
// ---------------------------------------------------------------------------
static constexpr int NSTAGE = 3;
static constexpr int STAGE_BYTES = A_TILE + B_TILE;   // 33792
static constexpr uint32_t STAGE_TX = (uint32_t)STAGE_BYTES;
static constexpr int SMEM_DYN = 1024 + NSTAGE * STAGE_BYTES;   // 102400

template <int EPI>
__global__ __launch_bounds__(128, 2)
void gemm_kernel(const float* __restrict__ bias, float* __restrict__ out_f32) {
    constexpr int KDIM  = EPI ? HID_F : IN_F;
    constexpr int NITER = KDIM / 64;
    const __half* A = EPI ? g_h  : g_x;
    const __half* B = EPI ? g_w2 : g_w1;

    extern __shared__ char smem_raw[];
    const uint32_t ctrl  = (smem_u32(smem_raw) + 15) & ~15u;
    const uint32_t sbase = (ctrl + 1023) & ~1023u;
    // full[s] = ctrl + 8*s ; empty[s] = ctrl + 24 + 8*s

    const int tid  = threadIdx.x;
    const int lane = tid & 31;
    const int warp = tid >> 5;
    const int wm   = warp & 1;    // 2 warps along M (64 rows each)
    const int wn   = warp >> 1;   // 2 warps along N (64 cols each)
    const int mBase = blockIdx.y * 128;
    const int nBase = blockIdx.x * 128;

    const char* gA = (const char*)(A + (size_t)blockIdx.y * (KDIM / 64) * A_TILE_H);
    const char* gB = (const char*)(B + (size_t)blockIdx.x * (KDIM / 64) * B_TILE_H);

    if (tid == 0) {
#pragma unroll
        for (int s = 0; s < NSTAGE; ++s) {
            mbar_init(ctrl + 8 * s, 1);        // full: completed by DMA tx
            mbar_init(ctrl + 24 + 8 * s, 128); // empty: all consumers arrive
        }
    }
    __syncthreads();

    float acc[4][8][4];   // [mt 16-rows][nt 8-cols][frag] = 128 regs
#pragma unroll
    for (int i = 0; i < 4; ++i)
#pragma unroll
        for (int j = 0; j < 8; ++j)
#pragma unroll
            for (int k = 0; k < 4; ++k) acc[i][j][k] = 0.0f;

    // prologue: all three stages in flight
    if (tid == 0) {
#pragma unroll
        for (int s = 0; s < NSTAGE; ++s) {
            const uint32_t mb = ctrl + 8 * s;
            const uint32_t As = sbase + s * STAGE_BYTES;
            mbar_expect_tx(mb, STAGE_TX);
            bulk_g2s(As,          gA + (size_t)s * A_TILE, A_TILE, mb);
            bulk_g2s(As + A_TILE, gB + (size_t)s * B_TILE, B_TILE, mb);
        }
    }

    const uint32_t aRowOff = (uint32_t)((wm * 64 + (lane & 15)) * 128 + ((lane >> 4) << 4));
    const int q = lane >> 3, r = lane & 7;
    const uint32_t bAddrBase = (uint32_t)(((q & 1) * 8 + r) * B_STRIDE
                                          + (wn * 64 + (q >> 1) * 8) * 2);

    int fph0 = 0, fph1 = 0, fph2 = 0;     // consumer full phases
    int eph0 = 0, eph1 = 0, eph2 = 0;     // producer empty phases (tid0)
    int s = 0;
#pragma unroll 1
    for (int it = 0; it < NITER; ++it) {
        const uint32_t fullB  = ctrl + 8 * s;
        const uint32_t emptyB = ctrl + 24 + 8 * s;
        if (s == 0)      { mbar_wait(fullB, fph0); fph0 ^= 1; }
        else if (s == 1) { mbar_wait(fullB, fph1); fph1 ^= 1; }
        else             { mbar_wait(fullB, fph2); fph2 ^= 1; }

        const uint32_t As = sbase + s * STAGE_BYTES;
        const uint32_t Bs = As + A_TILE;

#pragma unroll
        for (int ks = 0; ks < 4; ++ks) {
            uint32_t a[4][4], b[4][4];
#pragma unroll
            for (int mt = 0; mt < 4; ++mt)
                ldm4(a[mt], As + sw128(aRowOff + mt * 16 * 128 + ks * 32));
            const uint32_t bs = Bs + bAddrBase + (uint32_t)(ks * 16 * B_STRIDE);
#pragma unroll
            for (int nb = 0; nb < 4; ++nb)
                ldm4t(b[nb], bs + nb * 32);
#pragma unroll
            for (int mt = 0; mt < 4; ++mt)
#pragma unroll
                for (int nt = 0; nt < 8; ++nt) {
                    const uint32_t* bb = b[nt >> 1];
                    if (nt & 1) mma16816(acc[mt][nt], a[mt], bb[2], bb[3]);
                    else        mma16816(acc[mt][nt], a[mt], bb[0], bb[1]);
                }
        }

        // done reading stage s: non-blocking arrive, then free-run ahead
        mbar_arrive(emptyB);

        if (it + NSTAGE < NITER && tid == 0) {
            if (s == 0)      { mbar_wait(emptyB, eph0); eph0 ^= 1; }
            else if (s == 1) { mbar_wait(emptyB, eph1); eph1 ^= 1; }
            else             { mbar_wait(emptyB, eph2); eph2 ^= 1; }
            mbar_expect_tx(fullB, STAGE_TX);
            bulk_g2s(As,          gA + (size_t)(it + NSTAGE) * A_TILE, A_TILE, fullB);
            bulk_g2s(As + A_TILE, gB + (size_t)(it + NSTAGE) * B_TILE, B_TILE, fullB);
        }
        if (++s == NSTAGE) s = 0;
    }

    // epilogue
#pragma unroll
    for (int mt = 0; mt < 4; ++mt) {
#pragma unroll
        for (int nt = 0; nt < 8; ++nt) {
            const int col = nBase + wn * 64 + nt * 8 + (lane & 3) * 2;
            const float bv0 = __ldg(&bias[col]);
            const float bv1 = __ldg(&bias[col + 1]);
#pragma unroll
            for (int rr = 0; rr < 2; ++rr) {
                const int row = mBase + wm * 64 + mt * 16 + (lane >> 2) + rr * 8;
                float v0 = acc[mt][nt][rr * 2 + 0] + bv0;
                float v1 = acc[mt][nt][rr * 2 + 1] + bv1;
                if (EPI == 0) {
                    // write g_h in tiled+swizzled A-tile layout for GEMM2
                    __half2 h = __floats2half2_rn(fmaxf(v0, 0.0f), fmaxf(v1, 0.0f));
                    const int rr_ = row & 127;
                    const size_t tile = (size_t)(row >> 7) * (HID_F / 64) + (col >> 6);
                    const uint32_t inTile =
                        (uint32_t)(rr_ * 128 + (col & 63) * 2) ^ (uint32_t)((rr_ & 7) << 4);
                    *reinterpret_cast<__half2*>(
                        (char*)g_h + tile * A_TILE + inTile) = h;
                } else {
                    float2 o;
                    o.x = 1.0f / (1.0f + __expf(-v0));
                    o.y = 1.0f / (1.0f + __expf(-v1));
                    *reinterpret_cast<float2*>(&out_f32[(size_t)row * OUT_F + col]) = o;
                }
            }
        }
    }
}

// ---------------------------------------------------------------------------
extern "C" void kernel_launch(void* const* d_in, const int* in_sizes, int n_in,
                              void* d_out, int out_size) {
    (void)in_sizes; (void)n_in; (void)out_size;
    const float* x  = (const float*)d_in[0];
    const float* W1 = (const float*)d_in[1];
    const float* b1 = (const float*)d_in[2];
    const float* W2 = (const float*)d_in[3];
    const float* b2 = (const float*)d_in[4];
    float* out = (float*)d_out;

    cudaFuncSetAttribute(gemm_kernel<0>, cudaFuncAttributeMaxDynamicSharedMemorySize, SMEM_DYN);
    cudaFuncSetAttribute(gemm_kernel<1>, cudaFuncAttributeMaxDynamicSharedMemorySize, SMEM_DYN);

    // side stream + fork/join events (host-side objects; created per call,
    // intentionally not destroyed -- destruction mid-capture is illegal)
    cudaStream_t s2;
    cudaStreamCreateWithFlags(&s2, cudaStreamNonBlocking);
    cudaEvent_t eFork, eJoin;
    cudaEventCreateWithFlags(&eFork, cudaEventDisableTiming);
    cudaEventCreateWithFlags(&eJoin, cudaEventDisableTiming);

    // legacy stream: x and W1 converts (GEMM1 deps)
    convert_x_kernel<<<(BATCH * (IN_F / 8)) / 256, 256>>>(x);
    convert_w_kernel<1><<<(IN_F * (HID_F / 8)) / 256, 256>>>(W1);

    // fork: W2 convert runs on s2, concurrent with GEMM1 (GEMM1 is
    // compute-bound at 4% DRAM -> no bandwidth conflict)
    cudaEventRecord(eFork, 0);
    cudaStreamWaitEvent(s2, eFork, 0);
    convert_w_kernel<2><<<(HID_F * (OUT_F / 8)) / 256, 256, 0, s2>>>(W2);
    cudaEventRecord(eJoin, s2);

    // GEMM1: H = relu(x @ W1 + b1) -> fp16 g_h (tiled)
    gemm_kernel<0><<<dim3(HID_F / 128, BATCH / 128), 128, SMEM_DYN>>>(b1, nullptr);

    // join: GEMM2 needs g_h (legacy) and g_w2 (s2)
    cudaStreamWaitEvent(0, eJoin, 0);
    gemm_kernel<1><<<dim3(OUT_F / 128, BATCH / 128), 128, SMEM_DYN>>>(b2, out);
}